// round 8
// baseline (speedup 1.0000x reference)
#include <cuda_runtime.h>
#include <cuda_fp16.h>
#include <cuda_bf16.h>

// Problem constants
#define N_USERS 100000
#define N_ITEMS 100000
#define N_NODES 200000
#define D       64
#define NNZ     3200000
#define BATCH   500000

#define ND4 (N_NODES * D / 4)            // 3.2M 4-elem chunks
#define SCAN_BLK 256
#define NBLK_SCAN ((N_NODES + SCAN_BLK - 1) / SCAN_BLK)   // 782

// out = C0*b + C1*Ab + C2*A^2 b + C3*A^3 b   (exact expansion of the
// residual recurrence cur_k = 0.2 b + 0.8 A cur_{k-1}, out = b + sum cur_k)
#define C0 1.6f
#define C1 1.12f
#define C2 0.768f
#define C3 0.512f

// Edge value quantization: val in [0, 1/16), 14 bits -> step 1/262144
#define VAL_SCALE   262144.0f
#define VAL_INV     (1.0f / 262144.0f)

// Static device scratch (allocation-free rule).
// g_count / g_scan_ctr are zero at first launch (static zero-init) and
// restored to zero by the kernels that consume them, so every launch does
// identical work (graph-replay safe).
__device__ __half        g_h[3][N_NODES * D];   // h0=b, h1=Ab, h2=A^2 b
__device__ __half        g_out[N_NODES * D];    // 25.6 MB fp16
__device__ int           g_count[N_NODES];
__device__ int           g_rowstart[N_NODES];   // exclusive-within-scan-block
__device__ int           g_blocksum[NBLK_SCAN];
__device__ int           g_blockoff[NBLK_SCAN];
__device__ unsigned      g_scan_ctr;
__device__ unsigned char g_rank[NNZ];           // within-row rank, 3.2 MB
__device__ unsigned      g_epack[NNZ];          // col(18b) | valq(14b)<<18, 12.8 MB

#define ELEM_BLOCKS ((ND4 + 255) / 256)          // 12500
#define EDGE_BLOCKS ((NNZ + 255) / 256)          // 12500

// ---------------------------------------------------------------------------
// Phase A (fused, interleaved): even blocks convert tables -> h0 (fp16),
// odd blocks histogram rows + record within-row rank. Parity interleave keeps
// DRAM streaming and L2 atomics concurrently active in every wave.
// ---------------------------------------------------------------------------
__global__ __launch_bounds__(256) void init_hist_kernel(
    const float* __restrict__ user_table,
    const float* __restrict__ item_table,
    const int*   __restrict__ rows)
{
    int b = blockIdx.x;
    if ((b & 1) == 0) {
        int i = (b >> 1) * 256 + threadIdx.x;   // 4-elem chunk index
        if (i >= ND4) return;
        const int u4 = N_USERS * D / 4;
        float4 v;
        if (i < u4) v = reinterpret_cast<const float4*>(user_table)[i];
        else        v = reinterpret_cast<const float4*>(item_table)[i - u4];
        __half2 lo = __floats2half2_rn(v.x, v.y);
        __half2 hi = __floats2half2_rn(v.z, v.w);
        uint2 packed;
        packed.x = *reinterpret_cast<unsigned*>(&lo);
        packed.y = *reinterpret_cast<unsigned*>(&hi);
        reinterpret_cast<uint2*>(g_h[0])[i] = packed;
    } else {
        int e = (b >> 1) * 256 + threadIdx.x;
        if (e >= NNZ) return;
        int rank = atomicAdd(&g_count[rows[e]], 1);
        g_rank[e] = (unsigned char)rank;
    }
}

// ---------------------------------------------------------------------------
// Fused scan: each block does its local exclusive scan of g_count (re-zeroing
// it), publishes its block sum, then the LAST-arriving block scans the 782
// block sums into g_blockoff and resets the ticket counter.
// ---------------------------------------------------------------------------
__global__ __launch_bounds__(SCAN_BLK) void scan_kernel()
{
    __shared__ int sm[SCAN_BLK];
    __shared__ unsigned ticket;
    int t = threadIdx.x;
    int i = blockIdx.x * SCAN_BLK + t;
    int v = (i < N_NODES) ? g_count[i] : 0;
    if (i < N_NODES) g_count[i] = 0;
    sm[t] = v;
    __syncthreads();
    for (int off = 1; off < SCAN_BLK; off <<= 1) {
        int x = (t >= off) ? sm[t - off] : 0;
        __syncthreads();
        sm[t] += x;
        __syncthreads();
    }
    if (i < N_NODES) g_rowstart[i] = sm[t] - v;      // exclusive-within-block
    if (t == SCAN_BLK - 1) g_blocksum[blockIdx.x] = sm[t];

    // last-block-finishes top-level scan
    __threadfence();
    if (t == 0) ticket = atomicAdd(&g_scan_ctr, 1);
    __syncthreads();
    if (ticket != NBLK_SCAN - 1) return;

    int w[4];
    int sum = 0;
    #pragma unroll
    for (int k = 0; k < 4; ++k) {
        int idx = t * 4 + k;
        w[k] = (idx < NBLK_SCAN) ? g_blocksum[idx] : 0;
        sum += w[k];
    }
    sm[t] = sum;
    __syncthreads();
    for (int off = 1; off < 256; off <<= 1) {
        int x = (t >= off) ? sm[t - off] : 0;
        __syncthreads();
        sm[t] += x;
        __syncthreads();
    }
    int excl = sm[t] - sum;
    #pragma unroll
    for (int k = 0; k < 4; ++k) {
        int idx = t * 4 + k;
        if (idx < NBLK_SCAN) g_blockoff[idx] = excl;
        excl += w[k];
    }
    if (t == 0) g_scan_ctr = 0;                      // restore invariant
}

__device__ __forceinline__ int row_start(int r)
{
    return g_rowstart[r] + g_blockoff[r >> 8];
}

// ---------------------------------------------------------------------------
// scatter: p = rowstart(row) + rank -> packed 4-byte edge. No atomics.
// (bound by L1tex store wavefronts on random 4B stores; ~structural floor)
// ---------------------------------------------------------------------------
__global__ __launch_bounds__(256) void scatter_kernel(
    const int*   __restrict__ rows,
    const int*   __restrict__ cols,
    const float* __restrict__ vals)
{
    int t = blockIdx.x * 256 + threadIdx.x;
    if (t * 8 >= NNZ) return;
    int4   r0 = reinterpret_cast<const int4*>(rows)[2 * t];
    int4   r1 = reinterpret_cast<const int4*>(rows)[2 * t + 1];
    int4   c0 = reinterpret_cast<const int4*>(cols)[2 * t];
    int4   c1 = reinterpret_cast<const int4*>(cols)[2 * t + 1];
    float4 v0 = reinterpret_cast<const float4*>(vals)[2 * t];
    float4 v1 = reinterpret_cast<const float4*>(vals)[2 * t + 1];
    uint2  k8 = reinterpret_cast<const uint2*>(g_rank)[t];

    int   r[8] = {r0.x, r0.y, r0.z, r0.w, r1.x, r1.y, r1.z, r1.w};
    int   c[8] = {c0.x, c0.y, c0.z, c0.w, c1.x, c1.y, c1.z, c1.w};
    float v[8] = {v0.x, v0.y, v0.z, v0.w, v1.x, v1.y, v1.z, v1.w};
    int   k[8];
    k[0] =  k8.x        & 255; k[1] = (k8.x >> 8)  & 255;
    k[2] = (k8.x >> 16) & 255; k[3] = (k8.x >> 24) & 255;
    k[4] =  k8.y        & 255; k[5] = (k8.y >> 8)  & 255;
    k[6] = (k8.y >> 16) & 255; k[7] = (k8.y >> 24) & 255;

    int p[8];
    #pragma unroll
    for (int m = 0; m < 8; ++m)
        p[m] = g_rowstart[r[m]] + g_blockoff[r[m] >> 8] + k[m];
    #pragma unroll
    for (int m = 0; m < 8; ++m) {
        unsigned vq = (unsigned)__float2int_rn(v[m] * VAL_SCALE);
        if (vq > 16383u) vq = 16383u;
        g_epack[p[m]] = (unsigned)c[m] | (vq << 18);
    }
}

// ---------------------------------------------------------------------------
// gather-SpMM: y = A * src  (monomial form; no per-layer blend).
// One warp per row; lane owns a half2. A gathered row = one 128-byte line.
// Double-buffered edge-descriptor prefetch hides the epack->gather chain.
//   LAST==0: h[LAYER+1] = fp16(acc)
//   LAST==1: out = fp16(C0*h0 + C1*h1 + C2*h2 + C3*acc)
// ---------------------------------------------------------------------------
template <int LAYER, int LAST>
__global__ __launch_bounds__(256) void spmm_kernel()
{
    const __half* __restrict__ src = g_h[LAYER];
    int w    = (blockIdx.x * 256 + threadIdx.x) >> 5;   // row
    int lane = threadIdx.x & 31;
    if (w >= N_NODES) return;
    int s = row_start(w);
    int e = (w == N_NODES - 1) ? NNZ : row_start(w + 1);

    float2 acc = make_float2(0.f, 0.f);
    const unsigned* __restrict__ ep = g_epack;

    int j = s;
    unsigned qc[8];
    bool have = (j + 8 <= e);
    if (have) {
        #pragma unroll
        for (int k = 0; k < 8; ++k) qc[k] = ep[j + k];
    }
    while (have) {
        unsigned qn[8];
        bool more = (j + 16 <= e);
        if (more) {
            #pragma unroll
            for (int k = 0; k < 8; ++k) qn[k] = ep[j + 8 + k];
        }
        __half2 hh[8];
        #pragma unroll
        for (int k = 0; k < 8; ++k)
            hh[k] = *reinterpret_cast<const __half2*>(
                        src + (size_t)(qc[k] & 0x3FFFFu) * D + lane * 2);
        #pragma unroll
        for (int k = 0; k < 8; ++k) {
            float v = (float)(qc[k] >> 18) * VAL_INV;
            float2 x = __half22float2(hh[k]);
            acc.x = fmaf(v, x.x, acc.x);
            acc.y = fmaf(v, x.y, acc.y);
        }
        j += 8;
        #pragma unroll
        for (int k = 0; k < 8; ++k) qc[k] = qn[k];
        have = more;
    }
    for (; j < e; ++j) {
        unsigned q = ep[j];
        float v = (float)(q >> 18) * VAL_INV;
        __half2 h = *reinterpret_cast<const __half2*>(
                        src + (size_t)(q & 0x3FFFFu) * D + lane * 2);
        float2 x = __half22float2(h);
        acc.x = fmaf(v, x.x, acc.x);
        acc.y = fmaf(v, x.y, acc.y);
    }

    size_t off = (size_t)w * D + lane * 2;
    if (LAST) {
        float2 b  = __half22float2(*reinterpret_cast<const __half2*>(g_h[0] + off));
        float2 y1 = __half22float2(*reinterpret_cast<const __half2*>(g_h[1] + off));
        float2 y2 = __half22float2(*reinterpret_cast<const __half2*>(g_h[2] + off));
        float ox = C0 * b.x + C1 * y1.x + C2 * y2.x + C3 * acc.x;
        float oy = C0 * b.y + C1 * y1.y + C2 * y2.y + C3 * acc.y;
        *reinterpret_cast<__half2*>(g_out + off) = __floats2half2_rn(ox, oy);
    } else {
        *reinterpret_cast<__half2*>(g_h[LAYER + 1] + off) =
            __floats2half2_rn(acc.x, acc.y);
    }
}

// ---------------------------------------------------------------------------
// dot: result[p] = dot(out[users[p]], out[N_USERS+items[p]]) / 16
// 4 lanes per pair; each lane owns 2 x uint4 (32B) of each row. MLP=4/thread.
// ---------------------------------------------------------------------------
__device__ __forceinline__ float dot8h(uint4 a, uint4 b)
{
    float s = 0.f;
    float2 fa, fb;
    fa = __half22float2(*reinterpret_cast<__half2*>(&a.x));
    fb = __half22float2(*reinterpret_cast<__half2*>(&b.x));
    s += fa.x * fb.x + fa.y * fb.y;
    fa = __half22float2(*reinterpret_cast<__half2*>(&a.y));
    fb = __half22float2(*reinterpret_cast<__half2*>(&b.y));
    s += fa.x * fb.x + fa.y * fb.y;
    fa = __half22float2(*reinterpret_cast<__half2*>(&a.z));
    fb = __half22float2(*reinterpret_cast<__half2*>(&b.z));
    s += fa.x * fb.x + fa.y * fb.y;
    fa = __half22float2(*reinterpret_cast<__half2*>(&a.w));
    fb = __half22float2(*reinterpret_cast<__half2*>(&b.w));
    s += fa.x * fb.x + fa.y * fb.y;
    return s;
}

__global__ __launch_bounds__(256) void dot_kernel(
    const int* __restrict__ users,
    const int* __restrict__ items,
    float*     __restrict__ result)
{
    int t = blockIdx.x * 256 + threadIdx.x;
    int p    = t >> 2;
    int lane = t & 3;
    if (p >= BATCH) return;
    int u  = users[p];
    int it = items[p];
    const uint4* pa = reinterpret_cast<const uint4*>(g_out + (size_t)u * D);
    const uint4* pb = reinterpret_cast<const uint4*>(g_out + (size_t)(N_USERS + it) * D);
    uint4 a0 = pa[lane];
    uint4 a1 = pa[lane + 4];
    uint4 b0 = pb[lane];
    uint4 b1 = pb[lane + 4];
    float s = dot8h(a0, b0) + dot8h(a1, b1);
    s += __shfl_xor_sync(0xffffffffu, s, 1);
    s += __shfl_xor_sync(0xffffffffu, s, 2);
    if (lane == 0) result[p] = s * 0.0625f;
}

// ---------------------------------------------------------------------------
extern "C" void kernel_launch(void* const* d_in, const int* in_sizes, int n_in,
                              void* d_out, int out_size)
{
    const float* user_table = (const float*)d_in[0];
    const float* item_table = (const float*)d_in[1];
    const int*   rows       = (const int*)  d_in[2];
    const int*   cols       = (const int*)  d_in[3];
    const float* vals       = (const float*)d_in[4];
    const int*   users      = (const int*)  d_in[5];
    const int*   items      = (const int*)  d_in[6];
    float*       result     = (float*)d_out;
    (void)in_sizes; (void)n_in; (void)out_size;

    const int spmm_blocks    = (N_NODES * 32 + 255) / 256;   // 25000
    const int dot_blocks     = (BATCH * 4 + 255) / 256;      // 7813
    const int scatter_blocks = (NNZ / 8 + 255) / 256;        // 1563

    init_hist_kernel<<<ELEM_BLOCKS + EDGE_BLOCKS, 256>>>(user_table, item_table, rows);
    scan_kernel<<<NBLK_SCAN, SCAN_BLK>>>();
    scatter_kernel<<<scatter_blocks, 256>>>(rows, cols, vals);
    spmm_kernel<0, 0><<<spmm_blocks, 256>>>();
    spmm_kernel<1, 0><<<spmm_blocks, 256>>>();
    spmm_kernel<2, 1><<<spmm_blocks, 256>>>();
    dot_kernel<<<dot_blocks, 256>>>(users, items, result);
}

// round 9
// speedup vs baseline: 1.5844x; 1.5844x over previous
#include <cuda_runtime.h>
#include <cuda_fp16.h>
#include <cuda_bf16.h>

// Problem constants
#define N_USERS 100000
#define N_ITEMS 100000
#define N_NODES 200000
#define D       64
#define NNZ     3200000
#define BATCH   500000

#define ND4 (N_NODES * D / 4)            // 3.2M 4-elem chunks
#define SCAN_BLK 256
#define NBLK_SCAN ((N_NODES + SCAN_BLK - 1) / SCAN_BLK)   // 782

// out = C0*b + C1*Ab + C2*A^2 b + C3*A^3 b   (exact expansion of the
// residual recurrence cur_k = 0.2 b + 0.8 A cur_{k-1}, out = b + sum cur_k)
#define C0 1.6f
#define C1 1.12f
#define C2 0.768f
#define C3 0.512f

// Edge value quantization: val in [0, 1/16), 14 bits -> step 1/262144.
// The inner loop accumulates with the INTEGER-scaled value; VAL_INV is folded
// into the epilogue (one multiply per output element instead of per edge).
#define VAL_SCALE   262144.0f
#define VAL_INV     (1.0f / 262144.0f)

// Static device scratch (allocation-free rule).
// g_count / g_scan_ctr are zero at first launch (static zero-init) and
// restored to zero by the kernels that consume them (graph-replay safe).
__device__ __half        g_h[3][N_NODES * D];   // h0=b, h1=Ab, h2=A^2 b
__device__ __half        g_out[N_NODES * D];    // 25.6 MB fp16
__device__ int           g_count[N_NODES];
__device__ int           g_rowstart[N_NODES];   // exclusive-within-scan-block
__device__ int           g_blocksum[NBLK_SCAN];
__device__ int           g_blockoff[NBLK_SCAN];
__device__ unsigned      g_scan_ctr;
__device__ unsigned char g_rank[NNZ];           // within-row rank, 3.2 MB
__device__ unsigned      g_epack[NNZ];          // col(18b) | valq(14b)<<18, 12.8 MB

#define ELEM_BLOCKS ((ND4 + 255) / 256)          // 12500
#define EDGE_BLOCKS ((NNZ + 255) / 256)          // 12500

// ---------------------------------------------------------------------------
// Phase A (fused, interleaved): even blocks convert tables -> h0 (fp16),
// odd blocks histogram rows + record within-row rank.
// ---------------------------------------------------------------------------
__global__ __launch_bounds__(256) void init_hist_kernel(
    const float* __restrict__ user_table,
    const float* __restrict__ item_table,
    const int*   __restrict__ rows)
{
    int b = blockIdx.x;
    if ((b & 1) == 0) {
        int i = (b >> 1) * 256 + threadIdx.x;   // 4-elem chunk index
        if (i >= ND4) return;
        const int u4 = N_USERS * D / 4;
        float4 v;
        if (i < u4) v = reinterpret_cast<const float4*>(user_table)[i];
        else        v = reinterpret_cast<const float4*>(item_table)[i - u4];
        __half2 lo = __floats2half2_rn(v.x, v.y);
        __half2 hi = __floats2half2_rn(v.z, v.w);
        uint2 packed;
        packed.x = *reinterpret_cast<unsigned*>(&lo);
        packed.y = *reinterpret_cast<unsigned*>(&hi);
        reinterpret_cast<uint2*>(g_h[0])[i] = packed;
    } else {
        int e = (b >> 1) * 256 + threadIdx.x;
        if (e >= NNZ) return;
        int rank = atomicAdd(&g_count[rows[e]], 1);
        g_rank[e] = (unsigned char)rank;
    }
}

// ---------------------------------------------------------------------------
// Fused scan: per-block local exclusive scan of g_count (re-zeroing it),
// publish block sums; last-arriving block scans the 782 block sums.
// ---------------------------------------------------------------------------
__global__ __launch_bounds__(SCAN_BLK) void scan_kernel()
{
    __shared__ int sm[SCAN_BLK];
    __shared__ unsigned ticket;
    int t = threadIdx.x;
    int i = blockIdx.x * SCAN_BLK + t;
    int v = (i < N_NODES) ? g_count[i] : 0;
    if (i < N_NODES) g_count[i] = 0;
    sm[t] = v;
    __syncthreads();
    for (int off = 1; off < SCAN_BLK; off <<= 1) {
        int x = (t >= off) ? sm[t - off] : 0;
        __syncthreads();
        sm[t] += x;
        __syncthreads();
    }
    if (i < N_NODES) g_rowstart[i] = sm[t] - v;      // exclusive-within-block
    if (t == SCAN_BLK - 1) g_blocksum[blockIdx.x] = sm[t];

    __threadfence();
    if (t == 0) ticket = atomicAdd(&g_scan_ctr, 1);
    __syncthreads();
    if (ticket != NBLK_SCAN - 1) return;

    int w[4];
    int sum = 0;
    #pragma unroll
    for (int k = 0; k < 4; ++k) {
        int idx = t * 4 + k;
        w[k] = (idx < NBLK_SCAN) ? g_blocksum[idx] : 0;
        sum += w[k];
    }
    sm[t] = sum;
    __syncthreads();
    for (int off = 1; off < 256; off <<= 1) {
        int x = (t >= off) ? sm[t - off] : 0;
        __syncthreads();
        sm[t] += x;
        __syncthreads();
    }
    int excl = sm[t] - sum;
    #pragma unroll
    for (int k = 0; k < 4; ++k) {
        int idx = t * 4 + k;
        if (idx < NBLK_SCAN) g_blockoff[idx] = excl;
        excl += w[k];
    }
    if (t == 0) g_scan_ctr = 0;                      // restore invariant
}

__device__ __forceinline__ int row_start(int r)
{
    return g_rowstart[r] + g_blockoff[r >> 8];
}

// ---------------------------------------------------------------------------
// scatter: p = rowstart(row) + rank -> packed 4-byte edge. No atomics.
// (bound by L1tex store wavefronts on random 4B stores; ~structural floor)
// ---------------------------------------------------------------------------
__global__ __launch_bounds__(256) void scatter_kernel(
    const int*   __restrict__ rows,
    const int*   __restrict__ cols,
    const float* __restrict__ vals)
{
    int t = blockIdx.x * 256 + threadIdx.x;
    if (t * 8 >= NNZ) return;
    int4   r0 = reinterpret_cast<const int4*>(rows)[2 * t];
    int4   r1 = reinterpret_cast<const int4*>(rows)[2 * t + 1];
    int4   c0 = reinterpret_cast<const int4*>(cols)[2 * t];
    int4   c1 = reinterpret_cast<const int4*>(cols)[2 * t + 1];
    float4 v0 = reinterpret_cast<const float4*>(vals)[2 * t];
    float4 v1 = reinterpret_cast<const float4*>(vals)[2 * t + 1];
    uint2  k8 = reinterpret_cast<const uint2*>(g_rank)[t];

    int   r[8] = {r0.x, r0.y, r0.z, r0.w, r1.x, r1.y, r1.z, r1.w};
    int   c[8] = {c0.x, c0.y, c0.z, c0.w, c1.x, c1.y, c1.z, c1.w};
    float v[8] = {v0.x, v0.y, v0.z, v0.w, v1.x, v1.y, v1.z, v1.w};
    int   k[8];
    k[0] =  k8.x        & 255; k[1] = (k8.x >> 8)  & 255;
    k[2] = (k8.x >> 16) & 255; k[3] = (k8.x >> 24) & 255;
    k[4] =  k8.y        & 255; k[5] = (k8.y >> 8)  & 255;
    k[6] = (k8.y >> 16) & 255; k[7] = (k8.y >> 24) & 255;

    int p[8];
    #pragma unroll
    for (int m = 0; m < 8; ++m)
        p[m] = g_rowstart[r[m]] + g_blockoff[r[m] >> 8] + k[m];
    #pragma unroll
    for (int m = 0; m < 8; ++m) {
        unsigned vq = (unsigned)__float2int_rn(v[m] * VAL_SCALE);
        if (vq > 16383u) vq = 16383u;
        g_epack[p[m]] = (unsigned)c[m] | (vq << 18);
    }
}

// ---------------------------------------------------------------------------
// gather-SpMM: y = A * src, 4 rows per warp, 8-lane groups, lane owns a uint4
// (16B = 8 halves). One warp-instruction processes one edge of EACH of the 4
// rows -> ~2x fewer issue slots per edge than 1-row/warp. Groups with fewer
// edges run predicated (v=0, harmless row-0 gather) until the warp max.
//   LAST==0: h[LAYER+1] = fp16(acc * VAL_INV)
//   LAST==1: out = fp16(C0*h0 + C1*h1 + C2*h2 + (C3*VAL_INV)*acc)
// ---------------------------------------------------------------------------
__device__ __forceinline__ void accum8(float* acc, uint4 x, float v)
{
    float2 f;
    f = __half22float2(*reinterpret_cast<__half2*>(&x.x));
    acc[0] = fmaf(v, f.x, acc[0]); acc[1] = fmaf(v, f.y, acc[1]);
    f = __half22float2(*reinterpret_cast<__half2*>(&x.y));
    acc[2] = fmaf(v, f.x, acc[2]); acc[3] = fmaf(v, f.y, acc[3]);
    f = __half22float2(*reinterpret_cast<__half2*>(&x.z));
    acc[4] = fmaf(v, f.x, acc[4]); acc[5] = fmaf(v, f.y, acc[5]);
    f = __half22float2(*reinterpret_cast<__half2*>(&x.w));
    acc[6] = fmaf(v, f.x, acc[6]); acc[7] = fmaf(v, f.y, acc[7]);
}

template <int LAYER, int LAST>
__global__ __launch_bounds__(256) void spmm_kernel()
{
    const __half* __restrict__ src = g_h[LAYER];
    int W    = (blockIdx.x * 256 + threadIdx.x) >> 5;   // warp index
    int lane = threadIdx.x & 31;
    int grp  = lane >> 3;                                // 0..3: row group
    int subl = lane & 7;                                 // lane within group
    int r    = W * 4 + grp;                              // this group's row
    bool rowok = (r < N_NODES);
    int rc = rowok ? r : (N_NODES - 1);
    int s = row_start(rc);
    int e = rowok ? ((r == N_NODES - 1) ? NNZ : row_start(r + 1)) : s;

    float acc[8] = {0.f, 0.f, 0.f, 0.f, 0.f, 0.f, 0.f, 0.f};
    const unsigned* __restrict__ ep = g_epack;
    int j = s;
    while (__any_sync(0xffffffffu, j < e)) {
        bool a0 = (j     < e);
        bool a1 = (j + 1 < e);
        unsigned q0 = a0 ? ep[j]     : 0u;
        unsigned q1 = a1 ? ep[j + 1] : 0u;
        uint4 x0 = *reinterpret_cast<const uint4*>(
                       src + (size_t)(q0 & 0x3FFFFu) * D + subl * 8);
        uint4 x1 = *reinterpret_cast<const uint4*>(
                       src + (size_t)(q1 & 0x3FFFFu) * D + subl * 8);
        float v0 = (float)(q0 >> 18);   // integer-scaled; VAL_INV in epilogue
        float v1 = (float)(q1 >> 18);
        accum8(acc, x0, v0);
        accum8(acc, x1, v1);
        j += 2;
    }

    if (!rowok) return;
    size_t off = (size_t)r * D + subl * 8;   // halves; 16B-aligned
    if (LAST) {
        uint4 b4  = *reinterpret_cast<const uint4*>(g_h[0] + off);
        uint4 y14 = *reinterpret_cast<const uint4*>(g_h[1] + off);
        uint4 y24 = *reinterpret_cast<const uint4*>(g_h[2] + off);
        const unsigned* bp  = reinterpret_cast<const unsigned*>(&b4);
        const unsigned* y1p = reinterpret_cast<const unsigned*>(&y14);
        const unsigned* y2p = reinterpret_cast<const unsigned*>(&y24);
        uint4 outv;
        unsigned* op = reinterpret_cast<unsigned*>(&outv);
        const float c3s = C3 * VAL_INV;
        #pragma unroll
        for (int k = 0; k < 4; ++k) {
            float2 fb = __half22float2(*reinterpret_cast<const __half2*>(&bp[k]));
            float2 f1 = __half22float2(*reinterpret_cast<const __half2*>(&y1p[k]));
            float2 f2 = __half22float2(*reinterpret_cast<const __half2*>(&y2p[k]));
            float ox = C0 * fb.x + C1 * f1.x + C2 * f2.x + c3s * acc[2 * k];
            float oy = C0 * fb.y + C1 * f1.y + C2 * f2.y + c3s * acc[2 * k + 1];
            __half2 h = __floats2half2_rn(ox, oy);
            op[k] = *reinterpret_cast<unsigned*>(&h);
        }
        *reinterpret_cast<uint4*>(g_out + off) = outv;
    } else {
        uint4 outv;
        unsigned* op = reinterpret_cast<unsigned*>(&outv);
        #pragma unroll
        for (int k = 0; k < 4; ++k) {
            __half2 h = __floats2half2_rn(acc[2 * k] * VAL_INV,
                                          acc[2 * k + 1] * VAL_INV);
            op[k] = *reinterpret_cast<unsigned*>(&h);
        }
        *reinterpret_cast<uint4*>(g_h[LAYER + 1] + off) = outv;
    }
}

// ---------------------------------------------------------------------------
// dot: result[p] = dot(out[users[p]], out[N_USERS+items[p]]) / 16
// 4 lanes per pair; each lane owns 2 x uint4 (32B) of each row.
// ---------------------------------------------------------------------------
__device__ __forceinline__ float dot8h(uint4 a, uint4 b)
{
    float s = 0.f;
    float2 fa, fb;
    fa = __half22float2(*reinterpret_cast<__half2*>(&a.x));
    fb = __half22float2(*reinterpret_cast<__half2*>(&b.x));
    s += fa.x * fb.x + fa.y * fb.y;
    fa = __half22float2(*reinterpret_cast<__half2*>(&a.y));
    fb = __half22float2(*reinterpret_cast<__half2*>(&b.y));
    s += fa.x * fb.x + fa.y * fb.y;
    fa = __half22float2(*reinterpret_cast<__half2*>(&a.z));
    fb = __half22float2(*reinterpret_cast<__half2*>(&b.z));
    s += fa.x * fb.x + fa.y * fb.y;
    fa = __half22float2(*reinterpret_cast<__half2*>(&a.w));
    fb = __half22float2(*reinterpret_cast<__half2*>(&b.w));
    s += fa.x * fb.x + fa.y * fb.y;
    return s;
}

__global__ __launch_bounds__(256) void dot_kernel(
    const int* __restrict__ users,
    const int* __restrict__ items,
    float*     __restrict__ result)
{
    int t = blockIdx.x * 256 + threadIdx.x;
    int p    = t >> 2;
    int lane = t & 3;
    if (p >= BATCH) return;
    int u  = users[p];
    int it = items[p];
    const uint4* pa = reinterpret_cast<const uint4*>(g_out + (size_t)u * D);
    const uint4* pb = reinterpret_cast<const uint4*>(g_out + (size_t)(N_USERS + it) * D);
    uint4 a0 = pa[lane];
    uint4 a1 = pa[lane + 4];
    uint4 b0 = pb[lane];
    uint4 b1 = pb[lane + 4];
    float s = dot8h(a0, b0) + dot8h(a1, b1);
    s += __shfl_xor_sync(0xffffffffu, s, 1);
    s += __shfl_xor_sync(0xffffffffu, s, 2);
    if (lane == 0) result[p] = s * 0.0625f;
}

// ---------------------------------------------------------------------------
extern "C" void kernel_launch(void* const* d_in, const int* in_sizes, int n_in,
                              void* d_out, int out_size)
{
    const float* user_table = (const float*)d_in[0];
    const float* item_table = (const float*)d_in[1];
    const int*   rows       = (const int*)  d_in[2];
    const int*   cols       = (const int*)  d_in[3];
    const float* vals       = (const float*)d_in[4];
    const int*   users      = (const int*)  d_in[5];
    const int*   items      = (const int*)  d_in[6];
    float*       result     = (float*)d_out;
    (void)in_sizes; (void)n_in; (void)out_size;

    const int spmm_warps     = (N_NODES + 3) / 4;            // 50000
    const int spmm_blocks    = (spmm_warps + 7) / 8;         // 6250
    const int dot_blocks     = (BATCH * 4 + 255) / 256;      // 7813
    const int scatter_blocks = (NNZ / 8 + 255) / 256;        // 1563

    init_hist_kernel<<<ELEM_BLOCKS + EDGE_BLOCKS, 256>>>(user_table, item_table, rows);
    scan_kernel<<<NBLK_SCAN, SCAN_BLK>>>();
    scatter_kernel<<<scatter_blocks, 256>>>(rows, cols, vals);
    spmm_kernel<0, 0><<<spmm_blocks, 256>>>();
    spmm_kernel<1, 0><<<spmm_blocks, 256>>>();
    spmm_kernel<2, 1><<<spmm_blocks, 256>>>();
    dot_kernel<<<dot_blocks, 256>>>(users, items, result);
}

// round 10
// speedup vs baseline: 1.5959x; 1.0072x over previous
#include <cuda_runtime.h>
#include <cuda_fp16.h>
#include <cuda_bf16.h>

// Problem constants
#define N_USERS 100000
#define N_ITEMS 100000
#define N_NODES 200000
#define D       64
#define NNZ     3200000
#define BATCH   500000

#define ND4 (N_NODES * D / 4)            // 3.2M 4-elem chunks
#define SCAN_BLK 256
#define NBLK_SCAN ((N_NODES + SCAN_BLK - 1) / SCAN_BLK)   // 782
#define PERM_SIZE (NBLK_SCAN * SCAN_BLK)                  // 200192

// out = C0*b + C1*Ab + C2*A^2 b + C3*A^3 b   (exact expansion of the
// residual recurrence cur_k = 0.2 b + 0.8 A cur_{k-1}, out = b + sum cur_k)
#define C0 1.6f
#define C1 1.12f
#define C2 0.768f
#define C3 0.512f

// Edge value quantization: val in [0, 1/16), 14 bits -> step 1/262144.
// Inner loop accumulates with the INTEGER-scaled value; VAL_INV folded into
// the epilogue.
#define VAL_SCALE   262144.0f
#define VAL_INV     (1.0f / 262144.0f)

// Static device scratch (allocation-free rule).
// g_count / g_scan_ctr are zero at first launch (static zero-init) and
// restored to zero by the kernels that consume them (graph-replay safe).
__device__ __half        g_h[3][N_NODES * D];   // h0=b, h1=Ab, h2=A^2 b
__device__ __half        g_out[N_NODES * D];    // 25.6 MB fp16
__device__ int           g_count[N_NODES];
__device__ int           g_rowstart[N_NODES];   // exclusive-within-scan-block
__device__ int           g_blocksum[NBLK_SCAN];
__device__ int           g_blockoff[NBLK_SCAN];
__device__ int           g_perm[PERM_SIZE];     // degree-sorted row order
__device__ unsigned      g_scan_ctr;
__device__ unsigned char g_rank[NNZ];           // within-row rank, 3.2 MB
__device__ unsigned      g_epack[NNZ];          // col(18b) | valq(14b)<<18, 12.8 MB

#define ELEM_BLOCKS ((ND4 + 255) / 256)          // 12500
#define EDGE_BLOCKS ((NNZ + 255) / 256)          // 12500

// ---------------------------------------------------------------------------
// Phase A (fused, interleaved): even blocks convert tables -> h0 (fp16),
// odd blocks histogram rows + record within-row rank.
// ---------------------------------------------------------------------------
__global__ __launch_bounds__(256) void init_hist_kernel(
    const float* __restrict__ user_table,
    const float* __restrict__ item_table,
    const int*   __restrict__ rows)
{
    int b = blockIdx.x;
    if ((b & 1) == 0) {
        int i = (b >> 1) * 256 + threadIdx.x;   // 4-elem chunk index
        if (i >= ND4) return;
        const int u4 = N_USERS * D / 4;
        float4 v;
        if (i < u4) v = reinterpret_cast<const float4*>(user_table)[i];
        else        v = reinterpret_cast<const float4*>(item_table)[i - u4];
        __half2 lo = __floats2half2_rn(v.x, v.y);
        __half2 hi = __floats2half2_rn(v.z, v.w);
        uint2 packed;
        packed.x = *reinterpret_cast<unsigned*>(&lo);
        packed.y = *reinterpret_cast<unsigned*>(&hi);
        reinterpret_cast<uint2*>(g_h[0])[i] = packed;
    } else {
        int e = (b >> 1) * 256 + threadIdx.x;
        if (e >= NNZ) return;
        int rank = atomicAdd(&g_count[rows[e]], 1);
        g_rank[e] = (unsigned char)rank;
    }
}

// ---------------------------------------------------------------------------
// Fused scan + per-block degree sort:
//  1) local exclusive scan of g_count (re-zeroing it), publish block sums
//  2) counting-sort this block's 256 rows by degree -> g_perm (so spmm warps
//     get 4 near-equal-degree rows; kills within-warp divergence)
//  3) last-arriving block scans the 782 block sums into g_blockoff
// ---------------------------------------------------------------------------
__global__ __launch_bounds__(SCAN_BLK) void scan_kernel()
{
    __shared__ int sm[SCAN_BLK];
    __shared__ int hist[256];
    __shared__ int sc[256];
    __shared__ unsigned ticket;
    int t = threadIdx.x;
    int i = blockIdx.x * SCAN_BLK + t;
    bool valid = (i < N_NODES);
    int v = valid ? g_count[i] : 0;
    if (valid) g_count[i] = 0;
    sm[t] = v;
    __syncthreads();
    for (int off = 1; off < SCAN_BLK; off <<= 1) {
        int x = (t >= off) ? sm[t - off] : 0;
        __syncthreads();
        sm[t] += x;
        __syncthreads();
    }
    if (valid) g_rowstart[i] = sm[t] - v;            // exclusive-within-block
    if (t == SCAN_BLK - 1) g_blocksum[blockIdx.x] = sm[t];

    // ---- per-block counting sort by degree -> g_perm ----
    int deg = valid ? min(v, 255) : 255;             // invalid rows sort last
    hist[t] = 0;
    __syncthreads();
    atomicAdd(&hist[deg], 1);
    __syncthreads();
    int hv = hist[t];
    sc[t] = hv;
    __syncthreads();
    for (int off = 1; off < 256; off <<= 1) {
        int x = (t >= off) ? sc[t - off] : 0;
        __syncthreads();
        sc[t] += x;
        __syncthreads();
    }
    hist[t] = sc[t] - hv;                            // exclusive bin offsets
    __syncthreads();
    int pos = atomicAdd(&hist[deg], 1);
    g_perm[blockIdx.x * SCAN_BLK + pos] = valid ? i : -1;

    // ---- last-block top-level scan ----
    __threadfence();
    if (t == 0) ticket = atomicAdd(&g_scan_ctr, 1);
    __syncthreads();
    if (ticket != NBLK_SCAN - 1) return;

    int w[4];
    int sum = 0;
    #pragma unroll
    for (int k = 0; k < 4; ++k) {
        int idx = t * 4 + k;
        w[k] = (idx < NBLK_SCAN) ? g_blocksum[idx] : 0;
        sum += w[k];
    }
    sm[t] = sum;
    __syncthreads();
    for (int off = 1; off < 256; off <<= 1) {
        int x = (t >= off) ? sm[t - off] : 0;
        __syncthreads();
        sm[t] += x;
        __syncthreads();
    }
    int excl = sm[t] - sum;
    #pragma unroll
    for (int k = 0; k < 4; ++k) {
        int idx = t * 4 + k;
        if (idx < NBLK_SCAN) g_blockoff[idx] = excl;
        excl += w[k];
    }
    if (t == 0) g_scan_ctr = 0;                      // restore invariant
}

__device__ __forceinline__ int row_start(int r)
{
    return g_rowstart[r] + g_blockoff[r >> 8];
}

// ---------------------------------------------------------------------------
// scatter: p = rowstart(row) + rank -> packed 4-byte edge. No atomics.
// ---------------------------------------------------------------------------
__global__ __launch_bounds__(256) void scatter_kernel(
    const int*   __restrict__ rows,
    const int*   __restrict__ cols,
    const float* __restrict__ vals)
{
    int t = blockIdx.x * 256 + threadIdx.x;
    if (t * 8 >= NNZ) return;
    int4   r0 = reinterpret_cast<const int4*>(rows)[2 * t];
    int4   r1 = reinterpret_cast<const int4*>(rows)[2 * t + 1];
    int4   c0 = reinterpret_cast<const int4*>(cols)[2 * t];
    int4   c1 = reinterpret_cast<const int4*>(cols)[2 * t + 1];
    float4 v0 = reinterpret_cast<const float4*>(vals)[2 * t];
    float4 v1 = reinterpret_cast<const float4*>(vals)[2 * t + 1];
    uint2  k8 = reinterpret_cast<const uint2*>(g_rank)[t];

    int   r[8] = {r0.x, r0.y, r0.z, r0.w, r1.x, r1.y, r1.z, r1.w};
    int   c[8] = {c0.x, c0.y, c0.z, c0.w, c1.x, c1.y, c1.z, c1.w};
    float v[8] = {v0.x, v0.y, v0.z, v0.w, v1.x, v1.y, v1.z, v1.w};
    int   k[8];
    k[0] =  k8.x        & 255; k[1] = (k8.x >> 8)  & 255;
    k[2] = (k8.x >> 16) & 255; k[3] = (k8.x >> 24) & 255;
    k[4] =  k8.y        & 255; k[5] = (k8.y >> 8)  & 255;
    k[6] = (k8.y >> 16) & 255; k[7] = (k8.y >> 24) & 255;

    int p[8];
    #pragma unroll
    for (int m = 0; m < 8; ++m)
        p[m] = g_rowstart[r[m]] + g_blockoff[r[m] >> 8] + k[m];
    #pragma unroll
    for (int m = 0; m < 8; ++m) {
        unsigned vq = (unsigned)__float2int_rn(v[m] * VAL_SCALE);
        if (vq > 16383u) vq = 16383u;
        g_epack[p[m]] = (unsigned)c[m] | (vq << 18);
    }
}

// ---------------------------------------------------------------------------
// gather-SpMM: y = A * src. 4 rows per warp via g_perm (near-equal degrees),
// 8-lane groups, lane owns uint4 (16B = 8 halves). Packed f32x2 FMA
// accumulators (Blackwell fma.rn.f32x2) halve FFMA count. Fixed trip count
// from warp-max degree removes per-iter vote.
//   LAST==0: h[LAYER+1] = fp16(acc * VAL_INV)
//   LAST==1: out = fp16(C0*h0 + C1*h1 + C2*h2 + (C3*VAL_INV)*acc)
// ---------------------------------------------------------------------------
__device__ __forceinline__ void accum_packed(unsigned long long* acc,
                                             uint4 x, unsigned long long vv)
{
    const unsigned* xs = reinterpret_cast<const unsigned*>(&x);
    #pragma unroll
    for (int k = 0; k < 4; ++k) {
        float2 f = __half22float2(*reinterpret_cast<const __half2*>(&xs[k]));
        unsigned long long xf;
        asm("mov.b64 %0, {%1, %2};" : "=l"(xf) : "f"(f.x), "f"(f.y));
        asm("fma.rn.f32x2 %0, %1, %2, %0;" : "+l"(acc[k]) : "l"(xf), "l"(vv));
    }
}

template <int LAYER, int LAST>
__global__ __launch_bounds__(256) void spmm_kernel()
{
    const __half* __restrict__ src = g_h[LAYER];
    int W    = (blockIdx.x * 256 + threadIdx.x) >> 5;   // warp index
    int lane = threadIdx.x & 31;
    int grp  = lane >> 3;                                // 0..3: row group
    int subl = lane & 7;                                 // lane within group
    int idx  = W * 4 + grp;
    int r    = (idx < PERM_SIZE) ? g_perm[idx] : -1;
    bool rowok = (r >= 0);
    int rc = rowok ? r : 0;
    int s = rowok ? row_start(rc) : 0;
    int e = rowok ? ((rc == N_NODES - 1) ? NNZ : row_start(rc + 1)) : 0;

    // warp-max degree -> uniform trip count (degrees near-equal after sort)
    int deg = e - s;
    int mx = deg;
    mx = max(mx, __shfl_xor_sync(0xffffffffu, mx, 8));
    mx = max(mx, __shfl_xor_sync(0xffffffffu, mx, 16));
    int iters = (mx + 1) >> 1;

    unsigned long long acc[4] = {0ull, 0ull, 0ull, 0ull};
    const unsigned* __restrict__ ep = g_epack;
    int j = s;
    for (int it = 0; it < iters; ++it, j += 2) {
        unsigned q0 = (j     < e) ? ep[j]     : 0u;
        unsigned q1 = (j + 1 < e) ? ep[j + 1] : 0u;
        uint4 x0 = *reinterpret_cast<const uint4*>(
                       src + (size_t)(q0 & 0x3FFFFu) * D + subl * 8);
        uint4 x1 = *reinterpret_cast<const uint4*>(
                       src + (size_t)(q1 & 0x3FFFFu) * D + subl * 8);
        float v0 = (float)(q0 >> 18);   // integer-scaled; VAL_INV in epilogue
        float v1 = (float)(q1 >> 18);
        unsigned long long vv0, vv1;
        asm("mov.b64 %0, {%1, %2};" : "=l"(vv0) : "f"(v0), "f"(v0));
        asm("mov.b64 %0, {%1, %2};" : "=l"(vv1) : "f"(v1), "f"(v1));
        accum_packed(acc, x0, vv0);
        accum_packed(acc, x1, vv1);
    }

    if (!rowok) return;
    float a[8];
    #pragma unroll
    for (int k = 0; k < 4; ++k)
        asm("mov.b64 {%0, %1}, %2;" : "=f"(a[2 * k]), "=f"(a[2 * k + 1])
                                    : "l"(acc[k]));

    size_t off = (size_t)r * D + subl * 8;   // halves; 16B-aligned
    if (LAST) {
        uint4 b4  = *reinterpret_cast<const uint4*>(g_h[0] + off);
        uint4 y14 = *reinterpret_cast<const uint4*>(g_h[1] + off);
        uint4 y24 = *reinterpret_cast<const uint4*>(g_h[2] + off);
        const unsigned* bp  = reinterpret_cast<const unsigned*>(&b4);
        const unsigned* y1p = reinterpret_cast<const unsigned*>(&y14);
        const unsigned* y2p = reinterpret_cast<const unsigned*>(&y24);
        uint4 outv;
        unsigned* op = reinterpret_cast<unsigned*>(&outv);
        const float c3s = C3 * VAL_INV;
        #pragma unroll
        for (int k = 0; k < 4; ++k) {
            float2 fb = __half22float2(*reinterpret_cast<const __half2*>(&bp[k]));
            float2 f1 = __half22float2(*reinterpret_cast<const __half2*>(&y1p[k]));
            float2 f2 = __half22float2(*reinterpret_cast<const __half2*>(&y2p[k]));
            float ox = C0 * fb.x + C1 * f1.x + C2 * f2.x + c3s * a[2 * k];
            float oy = C0 * fb.y + C1 * f1.y + C2 * f2.y + c3s * a[2 * k + 1];
            __half2 h = __floats2half2_rn(ox, oy);
            op[k] = *reinterpret_cast<unsigned*>(&h);
        }
        *reinterpret_cast<uint4*>(g_out + off) = outv;
    } else {
        uint4 outv;
        unsigned* op = reinterpret_cast<unsigned*>(&outv);
        #pragma unroll
        for (int k = 0; k < 4; ++k) {
            __half2 h = __floats2half2_rn(a[2 * k] * VAL_INV,
                                          a[2 * k + 1] * VAL_INV);
            op[k] = *reinterpret_cast<unsigned*>(&h);
        }
        *reinterpret_cast<uint4*>(g_h[LAYER + 1] + off) = outv;
    }
}

// ---------------------------------------------------------------------------
// dot: result[p] = dot(out[users[p]], out[N_USERS+items[p]]) / 16
// 4 lanes per pair; each lane owns 2 x uint4 (32B) of each row.
// ---------------------------------------------------------------------------
__device__ __forceinline__ float dot8h(uint4 a, uint4 b)
{
    float s = 0.f;
    float2 fa, fb;
    fa = __half22float2(*reinterpret_cast<__half2*>(&a.x));
    fb = __half22float2(*reinterpret_cast<__half2*>(&b.x));
    s += fa.x * fb.x + fa.y * fb.y;
    fa = __half22float2(*reinterpret_cast<__half2*>(&a.y));
    fb = __half22float2(*reinterpret_cast<__half2*>(&b.y));
    s += fa.x * fb.x + fa.y * fb.y;
    fa = __half22float2(*reinterpret_cast<__half2*>(&a.z));
    fb = __half22float2(*reinterpret_cast<__half2*>(&b.z));
    s += fa.x * fb.x + fa.y * fb.y;
    fa = __half22float2(*reinterpret_cast<__half2*>(&a.w));
    fb = __half22float2(*reinterpret_cast<__half2*>(&b.w));
    s += fa.x * fb.x + fa.y * fb.y;
    return s;
}

__global__ __launch_bounds__(256) void dot_kernel(
    const int* __restrict__ users,
    const int* __restrict__ items,
    float*     __restrict__ result)
{
    int t = blockIdx.x * 256 + threadIdx.x;
    int p    = t >> 2;
    int lane = t & 3;
    if (p >= BATCH) return;
    int u  = users[p];
    int it = items[p];
    const uint4* pa = reinterpret_cast<const uint4*>(g_out + (size_t)u * D);
    const uint4* pb = reinterpret_cast<const uint4*>(g_out + (size_t)(N_USERS + it) * D);
    uint4 a0 = pa[lane];
    uint4 a1 = pa[lane + 4];
    uint4 b0 = pb[lane];
    uint4 b1 = pb[lane + 4];
    float s = dot8h(a0, b0) + dot8h(a1, b1);
    s += __shfl_xor_sync(0xffffffffu, s, 1);
    s += __shfl_xor_sync(0xffffffffu, s, 2);
    if (lane == 0) result[p] = s * 0.0625f;
}

// ---------------------------------------------------------------------------
extern "C" void kernel_launch(void* const* d_in, const int* in_sizes, int n_in,
                              void* d_out, int out_size)
{
    const float* user_table = (const float*)d_in[0];
    const float* item_table = (const float*)d_in[1];
    const int*   rows       = (const int*)  d_in[2];
    const int*   cols       = (const int*)  d_in[3];
    const float* vals       = (const float*)d_in[4];
    const int*   users      = (const int*)  d_in[5];
    const int*   items      = (const int*)  d_in[6];
    float*       result     = (float*)d_out;
    (void)in_sizes; (void)n_in; (void)out_size;

    const int spmm_warps     = PERM_SIZE / 4;                // 50048
    const int spmm_blocks    = (spmm_warps + 7) / 8;         // 6256
    const int dot_blocks     = (BATCH * 4 + 255) / 256;      // 7813
    const int scatter_blocks = (NNZ / 8 + 255) / 256;        // 1563

    init_hist_kernel<<<ELEM_BLOCKS + EDGE_BLOCKS, 256>>>(user_table, item_table, rows);
    scan_kernel<<<NBLK_SCAN, SCAN_BLK>>>();
    scatter_kernel<<<scatter_blocks, 256>>>(rows, cols, vals);
    spmm_kernel<0, 0><<<spmm_blocks, 256>>>();
    spmm_kernel<1, 0><<<spmm_blocks, 256>>>();
    spmm_kernel<2, 1><<<spmm_blocks, 256>>>();
    dot_kernel<<<dot_blocks, 256>>>(users, items, result);
}

// round 11
// speedup vs baseline: 1.5995x; 1.0023x over previous
#include <cuda_runtime.h>
#include <cuda_fp16.h>
#include <cuda_bf16.h>

// Problem constants
#define N_USERS 100000
#define N_ITEMS 100000
#define N_NODES 200000
#define D       64
#define NNZ     3200000
#define BATCH   500000

#define ND4 (N_NODES * D / 4)            // 3.2M 4-elem chunks
#define SCAN_BLK 256
#define NBLK_SCAN ((N_NODES + SCAN_BLK - 1) / SCAN_BLK)   // 782
#define PERM_SIZE (NBLK_SCAN * SCAN_BLK)                  // 200192

// out = C0*b + C1*Ab + C2*A^2 b + C3*A^3 b
#define C0 1.6f
#define C1 1.12f
#define C2 0.768f
#define C3 0.512f

// Edge value quantization: val in [0, 1/16), 14 bits -> step 1/262144.
#define VAL_SCALE   262144.0f
#define VAL_INV     (1.0f / 262144.0f)

// Static device scratch (allocation-free rule).
__device__ __half        g_h[3][N_NODES * D];   // h0=b, h1=Ab, h2=A^2 b
__device__ __half        g_out[N_NODES * D];    // 25.6 MB fp16
__device__ int           g_count[N_NODES];
__device__ int           g_rowstart[N_NODES];   // exclusive-within-scan-block
__device__ int           g_blocksum[NBLK_SCAN];
__device__ int           g_blockoff[NBLK_SCAN];
__device__ int           g_perm[PERM_SIZE];     // degree-sorted row order
__device__ unsigned      g_scan_ctr;
__device__ unsigned char g_rank[NNZ];           // within-row rank, 3.2 MB
__device__ unsigned      g_epack[NNZ];          // col(18b) | valq(14b)<<18

#define ELEM_BLOCKS ((ND4 + 255) / 256)          // 12500
#define EDGE_BLOCKS ((NNZ + 255) / 256)          // 12500

// ---------------------------------------------------------------------------
// Phase A (fused, interleaved): even blocks convert tables -> h0 (fp16),
// odd blocks histogram rows + record within-row rank.
// ---------------------------------------------------------------------------
__global__ __launch_bounds__(256) void init_hist_kernel(
    const float* __restrict__ user_table,
    const float* __restrict__ item_table,
    const int*   __restrict__ rows)
{
    int b = blockIdx.x;
    if ((b & 1) == 0) {
        int i = (b >> 1) * 256 + threadIdx.x;   // 4-elem chunk index
        if (i >= ND4) return;
        const int u4 = N_USERS * D / 4;
        float4 v;
        if (i < u4) v = reinterpret_cast<const float4*>(user_table)[i];
        else        v = reinterpret_cast<const float4*>(item_table)[i - u4];
        __half2 lo = __floats2half2_rn(v.x, v.y);
        __half2 hi = __floats2half2_rn(v.z, v.w);
        uint2 packed;
        packed.x = *reinterpret_cast<unsigned*>(&lo);
        packed.y = *reinterpret_cast<unsigned*>(&hi);
        reinterpret_cast<uint2*>(g_h[0])[i] = packed;
    } else {
        int e = (b >> 1) * 256 + threadIdx.x;
        if (e >= NNZ) return;
        int rank = atomicAdd(&g_count[rows[e]], 1);
        g_rank[e] = (unsigned char)rank;
    }
}

// ---------------------------------------------------------------------------
// Fused scan + per-block degree sort (see R9 comments).
// ---------------------------------------------------------------------------
__global__ __launch_bounds__(SCAN_BLK) void scan_kernel()
{
    __shared__ int sm[SCAN_BLK];
    __shared__ int hist[256];
    __shared__ int sc[256];
    __shared__ unsigned ticket;
    int t = threadIdx.x;
    int i = blockIdx.x * SCAN_BLK + t;
    bool valid = (i < N_NODES);
    int v = valid ? g_count[i] : 0;
    if (valid) g_count[i] = 0;
    sm[t] = v;
    __syncthreads();
    for (int off = 1; off < SCAN_BLK; off <<= 1) {
        int x = (t >= off) ? sm[t - off] : 0;
        __syncthreads();
        sm[t] += x;
        __syncthreads();
    }
    if (valid) g_rowstart[i] = sm[t] - v;            // exclusive-within-block
    if (t == SCAN_BLK - 1) g_blocksum[blockIdx.x] = sm[t];

    // ---- per-block counting sort by degree -> g_perm ----
    int deg = valid ? min(v, 255) : 255;             // invalid rows sort last
    hist[t] = 0;
    __syncthreads();
    atomicAdd(&hist[deg], 1);
    __syncthreads();
    int hv = hist[t];
    sc[t] = hv;
    __syncthreads();
    for (int off = 1; off < 256; off <<= 1) {
        int x = (t >= off) ? sc[t - off] : 0;
        __syncthreads();
        sc[t] += x;
        __syncthreads();
    }
    hist[t] = sc[t] - hv;                            // exclusive bin offsets
    __syncthreads();
    int pos = atomicAdd(&hist[deg], 1);
    g_perm[blockIdx.x * SCAN_BLK + pos] = valid ? i : -1;

    // ---- last-block top-level scan ----
    __threadfence();
    if (t == 0) ticket = atomicAdd(&g_scan_ctr, 1);
    __syncthreads();
    if (ticket != NBLK_SCAN - 1) return;

    int w[4];
    int sum = 0;
    #pragma unroll
    for (int k = 0; k < 4; ++k) {
        int idx = t * 4 + k;
        w[k] = (idx < NBLK_SCAN) ? g_blocksum[idx] : 0;
        sum += w[k];
    }
    sm[t] = sum;
    __syncthreads();
    for (int off = 1; off < 256; off <<= 1) {
        int x = (t >= off) ? sm[t - off] : 0;
        __syncthreads();
        sm[t] += x;
        __syncthreads();
    }
    int excl = sm[t] - sum;
    #pragma unroll
    for (int k = 0; k < 4; ++k) {
        int idx = t * 4 + k;
        if (idx < NBLK_SCAN) g_blockoff[idx] = excl;
        excl += w[k];
    }
    if (t == 0) g_scan_ctr = 0;                      // restore invariant
}

__device__ __forceinline__ int row_start(int r)
{
    return g_rowstart[r] + g_blockoff[r >> 8];
}

// ---------------------------------------------------------------------------
// scatter: p = rowstart(row) + rank -> packed 4-byte edge. No atomics.
// ---------------------------------------------------------------------------
__global__ __launch_bounds__(256) void scatter_kernel(
    const int*   __restrict__ rows,
    const int*   __restrict__ cols,
    const float* __restrict__ vals)
{
    int t = blockIdx.x * 256 + threadIdx.x;
    if (t * 8 >= NNZ) return;
    int4   r0 = reinterpret_cast<const int4*>(rows)[2 * t];
    int4   r1 = reinterpret_cast<const int4*>(rows)[2 * t + 1];
    int4   c0 = reinterpret_cast<const int4*>(cols)[2 * t];
    int4   c1 = reinterpret_cast<const int4*>(cols)[2 * t + 1];
    float4 v0 = reinterpret_cast<const float4*>(vals)[2 * t];
    float4 v1 = reinterpret_cast<const float4*>(vals)[2 * t + 1];
    uint2  k8 = reinterpret_cast<const uint2*>(g_rank)[t];

    int   r[8] = {r0.x, r0.y, r0.z, r0.w, r1.x, r1.y, r1.z, r1.w};
    int   c[8] = {c0.x, c0.y, c0.z, c0.w, c1.x, c1.y, c1.z, c1.w};
    float v[8] = {v0.x, v0.y, v0.z, v0.w, v1.x, v1.y, v1.z, v1.w};
    int   k[8];
    k[0] =  k8.x        & 255; k[1] = (k8.x >> 8)  & 255;
    k[2] = (k8.x >> 16) & 255; k[3] = (k8.x >> 24) & 255;
    k[4] =  k8.y        & 255; k[5] = (k8.y >> 8)  & 255;
    k[6] = (k8.y >> 16) & 255; k[7] = (k8.y >> 24) & 255;

    int p[8];
    #pragma unroll
    for (int m = 0; m < 8; ++m)
        p[m] = g_rowstart[r[m]] + g_blockoff[r[m] >> 8] + k[m];
    #pragma unroll
    for (int m = 0; m < 8; ++m) {
        unsigned vq = (unsigned)__float2int_rn(v[m] * VAL_SCALE);
        if (vq > 16383u) vq = 16383u;
        g_epack[p[m]] = (unsigned)c[m] | (vq << 18);
    }
}

// ---------------------------------------------------------------------------
// gather-SpMM: y = A * src. 4 rows per warp via g_perm (near-equal degrees),
// 8-lane groups, lane owns uint4 (16B = 8 halves). 4-edge unrolled iteration:
// all 4 descriptor loads, then all 4 gathers are issued before any consume ->
// MLP=4 gathers in flight per warp (covers L2-hit latency).
// Packed f32x2 FMA accumulators.
// ---------------------------------------------------------------------------
__device__ __forceinline__ void accum_packed(unsigned long long* acc,
                                             const uint4& x, unsigned long long vv)
{
    const unsigned* xs = reinterpret_cast<const unsigned*>(&x);
    #pragma unroll
    for (int k = 0; k < 4; ++k) {
        float2 f = __half22float2(*reinterpret_cast<const __half2*>(&xs[k]));
        unsigned long long xf;
        asm("mov.b64 %0, {%1, %2};" : "=l"(xf) : "f"(f.x), "f"(f.y));
        asm("fma.rn.f32x2 %0, %1, %2, %0;" : "+l"(acc[k]) : "l"(xf), "l"(vv));
    }
}

template <int LAYER, int LAST>
__global__ __launch_bounds__(256) void spmm_kernel()
{
    const __half* __restrict__ src = g_h[LAYER];
    int W    = (blockIdx.x * 256 + threadIdx.x) >> 5;   // warp index
    int lane = threadIdx.x & 31;
    int grp  = lane >> 3;                                // 0..3: row group
    int subl = lane & 7;                                 // lane within group
    int idx  = W * 4 + grp;
    int r    = (idx < PERM_SIZE) ? g_perm[idx] : -1;
    bool rowok = (r >= 0);
    int rc = rowok ? r : 0;
    int s = rowok ? row_start(rc) : 0;
    int e = rowok ? ((rc == N_NODES - 1) ? NNZ : row_start(rc + 1)) : 0;

    // warp-max degree -> uniform trip count (degrees near-equal after sort)
    int deg = e - s;
    int mx = deg;
    mx = max(mx, __shfl_xor_sync(0xffffffffu, mx, 8));
    mx = max(mx, __shfl_xor_sync(0xffffffffu, mx, 16));
    int iters = (mx + 3) >> 2;

    unsigned long long acc[4] = {0ull, 0ull, 0ull, 0ull};
    const unsigned* __restrict__ ep = g_epack;
    int j = s;
    for (int it = 0; it < iters; ++it, j += 4) {
        // 4 descriptor loads (independent)
        unsigned q0 = (j     < e) ? ep[j]     : 0u;
        unsigned q1 = (j + 1 < e) ? ep[j + 1] : 0u;
        unsigned q2 = (j + 2 < e) ? ep[j + 2] : 0u;
        unsigned q3 = (j + 3 < e) ? ep[j + 3] : 0u;
        // 4 gathers issued back-to-back (MLP=4 in flight)
        uint4 x0 = *reinterpret_cast<const uint4*>(
                       src + (size_t)(q0 & 0x3FFFFu) * D + subl * 8);
        uint4 x1 = *reinterpret_cast<const uint4*>(
                       src + (size_t)(q1 & 0x3FFFFu) * D + subl * 8);
        uint4 x2 = *reinterpret_cast<const uint4*>(
                       src + (size_t)(q2 & 0x3FFFFu) * D + subl * 8);
        uint4 x3 = *reinterpret_cast<const uint4*>(
                       src + (size_t)(q3 & 0x3FFFFu) * D + subl * 8);
        float v0 = (float)(q0 >> 18);   // integer-scaled; VAL_INV in epilogue
        float v1 = (float)(q1 >> 18);
        float v2 = (float)(q2 >> 18);
        float v3 = (float)(q3 >> 18);
        unsigned long long vv0, vv1, vv2, vv3;
        asm("mov.b64 %0, {%1, %1};" : "=l"(vv0) : "f"(v0));
        asm("mov.b64 %0, {%1, %1};" : "=l"(vv1) : "f"(v1));
        asm("mov.b64 %0, {%1, %1};" : "=l"(vv2) : "f"(v2));
        asm("mov.b64 %0, {%1, %1};" : "=l"(vv3) : "f"(v3));
        accum_packed(acc, x0, vv0);
        accum_packed(acc, x1, vv1);
        accum_packed(acc, x2, vv2);
        accum_packed(acc, x3, vv3);
    }

    if (!rowok) return;
    float a[8];
    #pragma unroll
    for (int k = 0; k < 4; ++k)
        asm("mov.b64 {%0, %1}, %2;" : "=f"(a[2 * k]), "=f"(a[2 * k + 1])
                                    : "l"(acc[k]));

    size_t off = (size_t)r * D + subl * 8;   // halves; 16B-aligned
    if (LAST) {
        uint4 b4  = *reinterpret_cast<const uint4*>(g_h[0] + off);
        uint4 y14 = *reinterpret_cast<const uint4*>(g_h[1] + off);
        uint4 y24 = *reinterpret_cast<const uint4*>(g_h[2] + off);
        const unsigned* bp  = reinterpret_cast<const unsigned*>(&b4);
        const unsigned* y1p = reinterpret_cast<const unsigned*>(&y14);
        const unsigned* y2p = reinterpret_cast<const unsigned*>(&y24);
        uint4 outv;
        unsigned* op = reinterpret_cast<unsigned*>(&outv);
        const float c3s = C3 * VAL_INV;
        #pragma unroll
        for (int k = 0; k < 4; ++k) {
            float2 fb = __half22float2(*reinterpret_cast<const __half2*>(&bp[k]));
            float2 f1 = __half22float2(*reinterpret_cast<const __half2*>(&y1p[k]));
            float2 f2 = __half22float2(*reinterpret_cast<const __half2*>(&y2p[k]));
            float ox = C0 * fb.x + C1 * f1.x + C2 * f2.x + c3s * a[2 * k];
            float oy = C0 * fb.y + C1 * f1.y + C2 * f2.y + c3s * a[2 * k + 1];
            __half2 h = __floats2half2_rn(ox, oy);
            op[k] = *reinterpret_cast<unsigned*>(&h);
        }
        *reinterpret_cast<uint4*>(g_out + off) = outv;
    } else {
        uint4 outv;
        unsigned* op = reinterpret_cast<unsigned*>(&outv);
        #pragma unroll
        for (int k = 0; k < 4; ++k) {
            __half2 h = __floats2half2_rn(a[2 * k] * VAL_INV,
                                          a[2 * k + 1] * VAL_INV);
            op[k] = *reinterpret_cast<unsigned*>(&h);
        }
        *reinterpret_cast<uint4*>(g_h[LAYER + 1] + off) = outv;
    }
}

// ---------------------------------------------------------------------------
// dot: result[p] = dot(out[users[p]], out[N_USERS+items[p]]) / 16
// ---------------------------------------------------------------------------
__device__ __forceinline__ float dot8h(uint4 a, uint4 b)
{
    float s = 0.f;
    float2 fa, fb;
    fa = __half22float2(*reinterpret_cast<__half2*>(&a.x));
    fb = __half22float2(*reinterpret_cast<__half2*>(&b.x));
    s += fa.x * fb.x + fa.y * fb.y;
    fa = __half22float2(*reinterpret_cast<__half2*>(&a.y));
    fb = __half22float2(*reinterpret_cast<__half2*>(&b.y));
    s += fa.x * fb.x + fa.y * fb.y;
    fa = __half22float2(*reinterpret_cast<__half2*>(&a.z));
    fb = __half22float2(*reinterpret_cast<__half2*>(&b.z));
    s += fa.x * fb.x + fa.y * fb.y;
    fa = __half22float2(*reinterpret_cast<__half2*>(&a.w));
    fb = __half22float2(*reinterpret_cast<__half2*>(&b.w));
    s += fa.x * fb.x + fa.y * fb.y;
    return s;
}

__global__ __launch_bounds__(256) void dot_kernel(
    const int* __restrict__ users,
    const int* __restrict__ items,
    float*     __restrict__ result)
{
    int t = blockIdx.x * 256 + threadIdx.x;
    int p    = t >> 2;
    int lane = t & 3;
    if (p >= BATCH) return;
    int u  = users[p];
    int it = items[p];
    const uint4* pa = reinterpret_cast<const uint4*>(g_out + (size_t)u * D);
    const uint4* pb = reinterpret_cast<const uint4*>(g_out + (size_t)(N_USERS + it) * D);
    uint4 a0 = pa[lane];
    uint4 a1 = pa[lane + 4];
    uint4 b0 = pb[lane];
    uint4 b1 = pb[lane + 4];
    float s = dot8h(a0, b0) + dot8h(a1, b1);
    s += __shfl_xor_sync(0xffffffffu, s, 1);
    s += __shfl_xor_sync(0xffffffffu, s, 2);
    if (lane == 0) result[p] = s * 0.0625f;
}

// ---------------------------------------------------------------------------
extern "C" void kernel_launch(void* const* d_in, const int* in_sizes, int n_in,
                              void* d_out, int out_size)
{
    const float* user_table = (const float*)d_in[0];
    const float* item_table = (const float*)d_in[1];
    const int*   rows       = (const int*)  d_in[2];
    const int*   cols       = (const int*)  d_in[3];
    const float* vals       = (const float*)d_in[4];
    const int*   users      = (const int*)  d_in[5];
    const int*   items      = (const int*)  d_in[6];
    float*       result     = (float*)d_out;
    (void)in_sizes; (void)n_in; (void)out_size;

    const int spmm_warps     = PERM_SIZE / 4;                // 50048
    const int spmm_blocks    = (spmm_warps + 7) / 8;         // 6256
    const int dot_blocks     = (BATCH * 4 + 255) / 256;      // 7813
    const int scatter_blocks = (NNZ / 8 + 255) / 256;        // 1563

    init_hist_kernel<<<ELEM_BLOCKS + EDGE_BLOCKS, 256>>>(user_table, item_table, rows);
    scan_kernel<<<NBLK_SCAN, SCAN_BLK>>>();
    scatter_kernel<<<scatter_blocks, 256>>>(rows, cols, vals);
    spmm_kernel<0, 0><<<spmm_blocks, 256>>>();
    spmm_kernel<1, 0><<<spmm_blocks, 256>>>();
    spmm_kernel<2, 1><<<spmm_blocks, 256>>>();
    dot_kernel<<<dot_blocks, 256>>>(users, items, result);
}